// round 17
// baseline (speedup 1.0000x reference)
#include <cuda_runtime.h>
#include <cuda_fp16.h>
#include <math.h>
#include <stdint.h>

// ---------------- problem constants ----------------
#define BB 8
#define TT 2048
#define VDIM 1024
#define ADIM 768
#define DM 256
#define HID 1024
#define MROWS (BB*TT)     /* 16384 */
#define XDIM (3*DM)       /* 768 */

// ---------------- device scratch ----------------
__device__ __align__(16) float g_v[MROWS*DM];      // LN'd video proj
__device__ __align__(16) float g_a[MROWS*DM];      // LN'd audio proj
__device__ __align__(16) float g_actx[MROWS*DM];
__device__ float g_rnv[MROWS];
__device__ float g_logits[MROWS];
// fp16 operands
__device__ __align__(16) __half g_vf[MROWS*VDIM];
__device__ __align__(16) __half g_af[MROWS*ADIM];
__device__ __align__(16) __half g_xf[MROWS*XDIM];
// transposed fp16 weights [N,K]
__device__ __align__(16) __half g_wv[DM*VDIM];
__device__ __align__(16) __half g_wa[DM*ADIM];
__device__ __align__(16) __half g_w1[HID*XDIM];

// ---------------- helpers ----------------
__device__ __forceinline__ float warp_sum(float v) {
#pragma unroll
    for (int o = 16; o > 0; o >>= 1) v += __shfl_xor_sync(0xffffffffu, v, o);
    return v;
}
__device__ __forceinline__ float gelu_exact(float x) {
    return 0.5f * x * (1.0f + erff(x * 0.70710678118654752f));
}
__device__ __forceinline__ void cp_async16(uint32_t dst, const void* src) {
    asm volatile("cp.async.cg.shared.global [%0], [%1], 16;" :: "r"(dst), "l"(src));
}
__device__ __forceinline__ void cp_commit() {
    asm volatile("cp.async.commit_group;" ::: "memory");
}
template<int N> __device__ __forceinline__ void cp_wait() {
    asm volatile("cp.async.wait_group %0;" :: "n"(N) : "memory");
}
__device__ __forceinline__ uint32_t smem_u32(const void* p) {
    uint32_t a;
    asm("{ .reg .u64 t; cvta.to.shared.u64 t, %1; cvt.u32.u64 %0, t; }" : "=r"(a) : "l"(p));
    return a;
}
__device__ __forceinline__ void mma_f16(float* c, const uint32_t* a, const uint32_t* b) {
    asm volatile(
        "mma.sync.aligned.m16n8k16.row.col.f32.f16.f16.f32 "
        "{%0,%1,%2,%3}, {%4,%5,%6,%7}, {%8,%9}, {%0,%1,%2,%3};"
        : "+f"(c[0]), "+f"(c[1]), "+f"(c[2]), "+f"(c[3])
        : "r"(a[0]), "r"(a[1]), "r"(a[2]), "r"(a[3]), "r"(b[0]), "r"(b[1]));
}
__device__ __forceinline__ void ldsm_x4(uint32_t* r, uint32_t addr) {
    asm volatile("ldmatrix.sync.aligned.m8n8.x4.shared.b16 {%0,%1,%2,%3}, [%4];"
        : "=r"(r[0]), "=r"(r[1]), "=r"(r[2]), "=r"(r[3]) : "r"(addr));
}

#define SROWB 144                      /* smem row stride bytes: 128 data + 16 pad */

// ================= MERGED projection GEMMs with fused LayerNorm =================
// blockIdx.y == 0: video (K=1024, rn written); == 1: audio (K=768).
// Tile 128x256, 512 threads = 16 warps (4 M x 4 N), warp tile 32x64, BK=64.
#define A_BYTES_LN (128*SROWB)             /* 18432 */
#define B_BYTES_LN (256*SROWB)             /* 36864 */
#define STAGE_LN   (A_BYTES_LN+B_BYTES_LN) /* 55296 */
#define SMEM_LN    (3*STAGE_LN)            /* 165888 */

__global__ void __launch_bounds__(512, 1) tc_gemm_ln2(
    const __half* __restrict__ Av, const __half* __restrict__ Bv,
    const float* __restrict__ biasv, float* __restrict__ Cv, float* __restrict__ rnv,
    const __half* __restrict__ Aa, const __half* __restrict__ Ba,
    const float* __restrict__ biasa, float* __restrict__ Ca)
{
    const int which = blockIdx.y;
    const __half* A    = which ? Aa : Av;
    const __half* B    = which ? Ba : Bv;
    const float*  bias = which ? biasa : biasv;
    float*        C    = which ? Ca : Cv;
    float*        rn   = which ? (float*)nullptr : rnv;
    const int     K    = which ? ADIM : VDIM;

    extern __shared__ __half smem[];
    uint32_t sbase = smem_u32(smem);
    const int tid    = threadIdx.x;
    const int wid    = tid >> 5;
    const int lane   = tid & 31;
    const int warp_m = wid >> 2;
    const int warp_n = wid & 3;
    const int lr     = lane >> 2;
    const int lc     = lane & 3;
    const int lr8    = lane & 7;
    const int lg     = lane >> 3;
    const int row0   = blockIdx.x * 128;

    const __half* Ap = A + (size_t)row0 * K;
    const int nk = K >> 6;

    uint32_t aoff[2], boff[4];
#pragma unroll
    for (int im = 0; im < 2; im++)
        aoff[im] = (uint32_t)((warp_m*32 + im*16 + (lg & 1)*8 + lr8) * SROWB + ((lg >> 1)*8) * 2);
#pragma unroll
    for (int ip = 0; ip < 4; ip++)
        boff[ip] = (uint32_t)((warp_n*64 + ip*16 + (lg >> 1)*8 + lr8) * SROWB + ((lg & 1)*8) * 2);

    auto load_stage = [&](int kt) {
        uint32_t sb = sbase + (uint32_t)(kt % 3) * STAGE_LN;
        int koff = kt * 64;
#pragma unroll
        for (int i = 0; i < 2; i++) {             // A: 1024 chunks
            int id = tid + i * 512;
            int r  = id >> 3, c = id & 7;
            cp_async16(sb + (uint32_t)(r * SROWB + c * 16),
                       Ap + (size_t)r * K + koff + c * 8);
        }
#pragma unroll
        for (int i = 0; i < 4; i++) {             // B: 2048 chunks
            int id = tid + i * 512;
            int r  = id >> 3, c = id & 7;
            cp_async16(sb + A_BYTES_LN + (uint32_t)(r * SROWB + c * 16),
                       B + (size_t)r * K + koff + c * 8);
        }
        cp_commit();
    };

    float acc[2][8][4];
#pragma unroll
    for (int im = 0; im < 2; im++)
#pragma unroll
        for (int in = 0; in < 8; in++)
#pragma unroll
            for (int j = 0; j < 4; j++) acc[im][in][j] = 0.f;

    load_stage(0);
    load_stage(1);

    for (int k = 0; k < nk; k++) {
        if (k == nk - 1) cp_wait<0>();
        else             cp_wait<1>();
        __syncthreads();
        if (k + 2 < nk) load_stage(k + 2);

        uint32_t sA = sbase + (uint32_t)(k % 3) * STAGE_LN;
        uint32_t sB = sA + A_BYTES_LN;

#pragma unroll
        for (int kk = 0; kk < 4; kk++) {
            uint32_t kb = (uint32_t)(kk * 32);
            uint32_t a[2][4], b[8][2];
#pragma unroll
            for (int im = 0; im < 2; im++)
                ldsm_x4(a[im], sA + aoff[im] + kb);
#pragma unroll
            for (int ip = 0; ip < 4; ip++) {
                uint32_t t[4];
                ldsm_x4(t, sB + boff[ip] + kb);
                b[2*ip][0] = t[0]; b[2*ip][1] = t[1];
                b[2*ip+1][0] = t[2]; b[2*ip+1][1] = t[3];
            }
#pragma unroll
            for (int im = 0; im < 2; im++)
#pragma unroll
                for (int in = 0; in < 8; in++)
                    mma_f16(acc[im][in], a[im], b[in]);
        }
    }

    // ---- LN epilogue ----
    float bcol[8][2];
#pragma unroll
    for (int in = 0; in < 8; in++) {
        int c = warp_n * 64 + in * 8 + lc * 2;
        bcol[in][0] = bias[c]; bcol[in][1] = bias[c + 1];
    }
#pragma unroll
    for (int im = 0; im < 2; im++)
#pragma unroll
        for (int in = 0; in < 8; in++) {
            acc[im][in][0] += bcol[in][0]; acc[im][in][1] += bcol[in][1];
            acc[im][in][2] += bcol[in][0]; acc[im][in][3] += bcol[in][1];
        }

    __syncthreads();
    float* part = (float*)smem;   // [128 rows][4 warp_n][2]

#pragma unroll
    for (int im = 0; im < 2; im++)
#pragma unroll
        for (int h = 0; h < 2; h++) {
            float s = 0.f, s2 = 0.f;
#pragma unroll
            for (int in = 0; in < 8; in++) {
                float v0 = acc[im][in][2*h], v1 = acc[im][in][2*h + 1];
                s += v0 + v1; s2 += v0*v0 + v1*v1;
            }
            s  += __shfl_xor_sync(0xffffffffu, s, 1);
            s  += __shfl_xor_sync(0xffffffffu, s, 2);
            s2 += __shfl_xor_sync(0xffffffffu, s2, 1);
            s2 += __shfl_xor_sync(0xffffffffu, s2, 2);
            if (lc == 0) {
                int r = warp_m*32 + im*16 + h*8 + lr;
                part[r*8 + warp_n*2]     = s;
                part[r*8 + warp_n*2 + 1] = s2;
            }
        }
    __syncthreads();

#pragma unroll
    for (int im = 0; im < 2; im++)
#pragma unroll
        for (int h = 0; h < 2; h++) {
            int r = warp_m*32 + im*16 + h*8 + lr;
            float S1 = part[r*8] + part[r*8+2] + part[r*8+4] + part[r*8+6];
            float S2 = part[r*8+1] + part[r*8+3] + part[r*8+5] + part[r*8+7];
            float mu = S1 * (1.0f / DM);
            float q  = fmaxf(S2 - S1 * mu, 0.f);
            float inv = 1.0f / sqrtf(q * (1.0f / DM) + 1e-5f);
            if (rn && warp_n == 0 && lc == 0)
                rn[row0 + r] = 1.0f / fmaxf(sqrtf(q) * inv, 1e-8f);
#pragma unroll
            for (int in = 0; in < 8; in++) {
                float2 o;
                o.x = (acc[im][in][2*h]     - mu) * inv;
                o.y = (acc[im][in][2*h + 1] - mu) * inv;
                int c = warp_n * 64 + in * 8 + lc * 2;
                *(float2*)&C[(size_t)(row0 + r) * DM + c] = o;
            }
        }
}

// ====== MLP GEMM: gelu + fused h@W2 partial dot -> atomicAdd(logits) ======
#define OP_BYTES (128*SROWB)           /* 18432 B per operand */
#define STAGE_BYTES (2*OP_BYTES)       /* 36864 B */
#define SMEM_GELU (3*STAGE_BYTES)      /* 110592 B */

__global__ void __launch_bounds__(256, 2) tc_gemm_gelu_dot(
    const __half* __restrict__ A, const __half* __restrict__ B,
    const float* __restrict__ bias, const float* __restrict__ W2,
    float* __restrict__ logits, int K)
{
    extern __shared__ __half smem[];
    uint32_t sbase = smem_u32(smem);
    const int tid    = threadIdx.x;
    const int wid    = tid >> 5;
    const int lane   = tid & 31;
    const int warp_m = wid >> 1;
    const int warp_n = wid & 1;
    const int lr     = lane >> 2;
    const int lc     = lane & 3;
    const int lr8    = lane & 7;
    const int lg     = lane >> 3;
    const int row0   = blockIdx.y * 128;
    const int col0   = blockIdx.x * 128;

    const __half* Ap = A + (size_t)row0 * K;
    const __half* Bp = B + (size_t)col0 * K;
    const int nk = K >> 6;

    uint32_t aoff[2], boff[4];
#pragma unroll
    for (int im = 0; im < 2; im++)
        aoff[im] = (uint32_t)((warp_m*32 + im*16 + (lg & 1)*8 + lr8) * SROWB + ((lg >> 1)*8) * 2);
#pragma unroll
    for (int ip = 0; ip < 4; ip++)
        boff[ip] = (uint32_t)((warp_n*64 + ip*16 + (lg >> 1)*8 + lr8) * SROWB + ((lg & 1)*8) * 2);

    auto load_stage = [&](int kt) {
        uint32_t sb = sbase + (uint32_t)(kt % 3) * STAGE_BYTES;
        int koff = kt * 64;
#pragma unroll
        for (int i = 0; i < 4; i++) {
            int id = tid + i * 256;
            int r  = id >> 3, c = id & 7;
            uint32_t soff = (uint32_t)(r * SROWB + c * 16);
            size_t   goff = (size_t)r * K + koff + c * 8;
            cp_async16(sb +            soff, Ap + goff);
            cp_async16(sb + OP_BYTES + soff, Bp + goff);
        }
        cp_commit();
    };

    float acc[2][8][4];
#pragma unroll
    for (int im = 0; im < 2; im++)
#pragma unroll
        for (int in = 0; in < 8; in++)
#pragma unroll
            for (int j = 0; j < 4; j++) acc[im][in][j] = 0.f;

    load_stage(0);
    load_stage(1);

    for (int k = 0; k < nk; k++) {
        if (k == nk - 1) cp_wait<0>();
        else             cp_wait<1>();
        __syncthreads();
        if (k + 2 < nk) load_stage(k + 2);

        uint32_t sA = sbase + (uint32_t)(k % 3) * STAGE_BYTES;
        uint32_t sB = sA + OP_BYTES;

#pragma unroll
        for (int kk = 0; kk < 4; kk++) {
            uint32_t kb = (uint32_t)(kk * 32);
            uint32_t a[2][4], b[8][2];
#pragma unroll
            for (int im = 0; im < 2; im++)
                ldsm_x4(a[im], sA + aoff[im] + kb);
#pragma unroll
            for (int ip = 0; ip < 4; ip++) {
                uint32_t t[4];
                ldsm_x4(t, sB + boff[ip] + kb);
                b[2*ip][0] = t[0]; b[2*ip][1] = t[1];
                b[2*ip+1][0] = t[2]; b[2*ip+1][1] = t[3];
            }
#pragma unroll
            for (int im = 0; im < 2; im++)
#pragma unroll
                for (int in = 0; in < 8; in++)
                    mma_f16(acc[im][in], a[im], b[in]);
        }
    }

    // epilogue: gelu(acc+bias) dotted with W2 -> per-row partial -> atomicAdd
    float bc[8][2], w2[8][2];
#pragma unroll
    for (int in = 0; in < 8; in++) {
        int c = col0 + warp_n * 64 + in * 8 + lc * 2;
        bc[in][0] = bias[c];       bc[in][1] = bias[c + 1];
        w2[in][0] = __ldg(&W2[c]); w2[in][1] = __ldg(&W2[c + 1]);
    }
#pragma unroll
    for (int im = 0; im < 2; im++)
#pragma unroll
        for (int h = 0; h < 2; h++) {
            float s = 0.f;
#pragma unroll
            for (int in = 0; in < 8; in++) {
                float g0 = gelu_exact(acc[im][in][2*h]     + bc[in][0]);
                float g1 = gelu_exact(acc[im][in][2*h + 1] + bc[in][1]);
                s = fmaf(g0, w2[in][0], s);
                s = fmaf(g1, w2[in][1], s);
            }
            s += __shfl_xor_sync(0xffffffffu, s, 1);
            s += __shfl_xor_sync(0xffffffffu, s, 2);
            if (lc == 0) {
                int r = row0 + warp_m*32 + im*16 + h*8 + lr;
                atomicAdd(&logits[r], s);
            }
        }
}

// ---------------- zero logits ----------------
__global__ void __launch_bounds__(256) zero_kernel(float* __restrict__ p, int n)
{
    int i = blockIdx.x * 256 + threadIdx.x;
    if (i < n) p[i] = 0.f;
}

// ---------------- pre-pass: convert fp32 -> fp16 ----------------
__global__ void __launch_bounds__(256) cvt_kernel(
    const float* __restrict__ X, __half* __restrict__ H, int n4)
{
    int i = blockIdx.x * 256 + threadIdx.x;
    if (i >= n4) return;
    float4 x = ((const float4*)X)[i];
    __half h[4] = {__float2half(x.x), __float2half(x.y),
                   __float2half(x.z), __float2half(x.w)};
    ((uint2*)H)[i] = *(uint2*)h;
}

// ---------------- pre-pass: transpose + convert weights [K,N] -> [N,K] fp16 ----------------
__global__ void __launch_bounds__(256) wcvt_kernel(
    const float* __restrict__ W, __half* __restrict__ Ht, int K, int N)
{
    int i = blockIdx.x * 256 + threadIdx.x;
    if (i >= K * N) return;
    int k = i / N, n = i % N;
    Ht[(size_t)n * K + k] = __float2half(W[i]);
}

// ---- fused: fractional shift + box avg (running-sum) + rnorm + build x ----
__global__ void __launch_bounds__(256) shiftbuildx_kernel(
    const float* __restrict__ A, const float* __restrict__ V,
    const float* __restrict__ rnv, float* __restrict__ Actx,
    __half* __restrict__ XH, const float* __restrict__ theta)
{
    int row  = blockIdx.x * 8 + (threadIdx.x >> 5);
    int lane = threadIdx.x & 31;
    int b = row / TT, t = row % TT;

    float th    = fminf(fmaxf(theta[0], -12.0f), 12.0f);
    float delta = 2.0f + 4.0f / (1.0f + expf(-th));
    float dl    = fminf(fmaxf(delta, 0.0f), (float)(TT - 1));
    float nf    = floorf(dl);
    float alpha = dl - nf;
    int   ni    = (int)nf;

    float center = fminf(fmaxf((float)t + delta, 0.0f), (float)t);
    int lo = max(0, (int)ceilf(center - 5.0f));
    int hi = min(t, (int)floorf(center + 5.0f));

    const float* base = A + (size_t)b * TT * DM + lane * 8;
    float acc[8] = {0,0,0,0,0,0,0,0};
    float w0 = 1.0f - alpha, w1 = alpha;

    int j0 = lo - ni, j1 = hi - ni;     // index range for the i0 stream
    if (j0 >= 0 && j1 + 1 <= TT - 1) {
        // fast path: no clamping anywhere.
        // sum0 = Σ_{j=j0..j1} a[j]; sum1 = sum0 - a[j0] + a[j1+1]
        // result = w0*sum0 + w1*sum1 = sum0 + w1*(a[j1+1] - a[j0])
        for (int j = j0; j <= j1; j++) {
            const float* p = base + (size_t)j * DM;
            float4 xa = *(const float4*)p, xb = *(const float4*)(p + 4);
            acc[0] += xa.x; acc[1] += xa.y; acc[2] += xa.z; acc[3] += xa.w;
            acc[4] += xb.x; acc[5] += xb.y; acc[6] += xb.z; acc[7] += xb.w;
        }
        const float* pl = base + (size_t)j0 * DM;
        const float* pr = base + (size_t)(j1 + 1) * DM;
        float4 la = *(const float4*)pl, lb = *(const float4*)(pl + 4);
        float4 ra = *(const float4*)pr, rb = *(const float4*)(pr + 4);
        acc[0] += w1 * (ra.x - la.x); acc[1] += w1 * (ra.y - la.y);
        acc[2] += w1 * (ra.z - la.z); acc[3] += w1 * (ra.w - la.w);
        acc[4] += w1 * (rb.x - lb.x); acc[5] += w1 * (rb.y - lb.y);
        acc[6] += w1 * (rb.z - lb.z); acc[7] += w1 * (rb.w - lb.w);
    } else {
        // slow path (edge rows): exact per-tap clamped interpolation
        for (int tau = lo; tau <= hi; tau++) {
            int i0 = min(max(tau - ni, 0), TT - 1);
            int i1 = min(i0 + 1, TT - 1);
            const float* p0 = base + (size_t)i0 * DM;
            const float* p1 = base + (size_t)i1 * DM;
            float4 x0a = *(const float4*)p0, x0b = *(const float4*)(p0 + 4);
            float4 x1a = *(const float4*)p1, x1b = *(const float4*)(p1 + 4);
            acc[0] += w0*x0a.x + w1*x1a.x; acc[1] += w0*x0a.y + w1*x1a.y;
            acc[2] += w0*x0a.z + w1*x1a.z; acc[3] += w0*x0a.w + w1*x1a.w;
            acc[4] += w0*x0b.x + w1*x1b.x; acc[5] += w0*x0b.y + w1*x1b.y;
            acc[6] += w0*x0b.z + w1*x1b.z; acc[7] += w0*x0b.w + w1*x1b.w;
        }
    }
    float scale = 1.0f / fmaxf((float)(hi - lo + 1), 1e-8f);
#pragma unroll
    for (int i = 0; i < 8; i++) acc[i] *= scale;

    float* ao = Actx + (size_t)row * DM + lane * 8;
    *(float4*)ao       = *(float4*)&acc[0];
    *(float4*)(ao + 4) = *(float4*)&acc[4];

    float q = 0.f;
#pragma unroll
    for (int i = 0; i < 8; i++) q += acc[i] * acc[i];
    q = warp_sum(q);
    float ra_ = 1.0f / fmaxf(sqrtf(q), 1e-8f);
    float rv = rnv[row];

    const float* vr = V + (size_t)row * DM + lane * 8;
    float v[8];
    *(float4*)&v[0] = *(const float4*)vr;
    *(float4*)&v[4] = *(const float4*)(vr + 4);

    __half an[8], vn[8], pr2[8];
#pragma unroll
    for (int i = 0; i < 8; i++) {
        float anf = acc[i] * ra_, vnf = v[i] * rv;
        an[i]  = __float2half(anf);
        vn[i]  = __float2half(vnf);
        pr2[i] = __float2half(anf * vnf);
    }
    size_t xb2 = (size_t)row * XDIM + lane * 8;
    *(uint4*)&XH[xb2]        = *(uint4*)an;
    *(uint4*)&XH[xb2 + DM]   = *(uint4*)vn;
    *(uint4*)&XH[xb2 + 2*DM] = *(uint4*)pr2;
}

// ---------------- final: gate from logits, blend (warp per row) ----------------
__global__ void __launch_bounds__(256) final_kernel(
    const float* __restrict__ logits, const float* __restrict__ Actx,
    const float* __restrict__ V, const float* __restrict__ b2,
    float* __restrict__ Out)
{
    int row  = blockIdx.x * 8 + (threadIdx.x >> 5);
    int lane = threadIdx.x & 31;

    float logit = fminf(fmaxf(logits[row] + b2[0], -12.0f), 12.0f);
    float g = 1.0f / (1.0f + expf(-logit));
    g = fminf(fmaxf(g, 0.05f), 0.95f);
    float om = 1.0f - g;

    const float4* av = (const float4*)(Actx + (size_t)row * DM);
    const float4* vv = (const float4*)(V    + (size_t)row * DM);
    float4*       ov = (float4*)(Out + (size_t)row * DM);
#pragma unroll
    for (int j = 0; j < 2; j++) {
        int d4 = lane * 2 + j;
        float4 a = av[d4], v = vv[d4];
        ov[d4] = make_float4(g*a.x + om*v.x, g*a.y + om*v.y,
                             g*a.z + om*v.z, g*a.w + om*v.w);
    }
}

// ---------------- launch ----------------
extern "C" void kernel_launch(void* const* d_in, const int* in_sizes, int n_in,
                              void* d_out, int out_size)
{
    const float* video = (const float*)d_in[0];
    const float* audio = (const float*)d_in[1];
    const float* Wv    = (const float*)d_in[2];
    const float* bv    = (const float*)d_in[3];
    const float* Wa    = (const float*)d_in[4];
    const float* ba    = (const float*)d_in[5];
    const float* theta = (const float*)d_in[6];
    const float* W1    = (const float*)d_in[7];
    const float* b1    = (const float*)d_in[8];
    const float* W2    = (const float*)d_in[9];
    const float* b2    = (const float*)d_in[10];
    float* out = (float*)d_out;

    float *pv, *pa, *pactx, *prnv, *plog;
    __half *pvf, *paf, *pxf, *pwv, *pwa, *pw1;
    cudaGetSymbolAddress((void**)&pv,    g_v);
    cudaGetSymbolAddress((void**)&pa,    g_a);
    cudaGetSymbolAddress((void**)&pactx, g_actx);
    cudaGetSymbolAddress((void**)&prnv,  g_rnv);
    cudaGetSymbolAddress((void**)&plog,  g_logits);
    cudaGetSymbolAddress((void**)&pvf,   g_vf);
    cudaGetSymbolAddress((void**)&paf,   g_af);
    cudaGetSymbolAddress((void**)&pxf,   g_xf);
    cudaGetSymbolAddress((void**)&pwv,   g_wv);
    cudaGetSymbolAddress((void**)&pwa,   g_wa);
    cudaGetSymbolAddress((void**)&pw1,   g_w1);

    cudaFuncSetAttribute(tc_gemm_ln2,      cudaFuncAttributeMaxDynamicSharedMemorySize, SMEM_LN);
    cudaFuncSetAttribute(tc_gemm_gelu_dot, cudaFuncAttributeMaxDynamicSharedMemorySize, SMEM_GELU);

    cvt_kernel<<<(MROWS*VDIM/4 + 255)/256, 256>>>(video, pvf, MROWS*VDIM/4);             // 1
    cvt_kernel<<<(MROWS*ADIM/4 + 255)/256, 256>>>(audio, paf, MROWS*ADIM/4);             // 2
    wcvt_kernel<<<(VDIM*DM + 255)/256, 256>>>(Wv, pwv, VDIM, DM);                        // 3
    wcvt_kernel<<<(ADIM*DM + 255)/256, 256>>>(Wa, pwa, ADIM, DM);                        // 4
    tc_gemm_ln2<<<dim3(MROWS/128, 2), 512, SMEM_LN>>>(                                   // 5
        pvf, pwv, bv, pv, prnv, paf, pwa, ba, pa);
    wcvt_kernel<<<(XDIM*HID + 255)/256, 256>>>(W1, pw1, XDIM, HID);                      // 6
    zero_kernel<<<MROWS/256, 256>>>(plog, MROWS);                                        // 7
    shiftbuildx_kernel<<<MROWS/8, 256>>>(pa, pv, prnv, pactx, pxf, theta);               // 8
    tc_gemm_gelu_dot<<<dim3(HID/128, MROWS/128), 256, SMEM_GELU>>>(                      // 9
        pxf, pw1, b1, W2, plog, XDIM);
    final_kernel<<<MROWS/8, 256>>>(plog, pactx, pv, b2, out);                            // 10
}